// round 15
// baseline (speedup 1.0000x reference)
#include <cuda_runtime.h>
#include <cstdint>

#define SPLITS    4
#define T1THREADS 256
#define T2THREADS 256
#define TOPN      64
#define CAP       1024
#define MAXB      128
#define T_INIT    6.0f

__device__ unsigned long long gCand[MAXB * CAP];
__device__ float gPart[MAXB * SPLITS];
__device__ int   gCnt[MAXB];

__device__ __forceinline__ uint32_t f2key(float x) {
    uint32_t u = __float_as_uint(x);
    return (u & 0x80000000u) ? ~u : (u | 0x80000000u);
}
__device__ __forceinline__ float key2f(uint32_t k) {
    uint32_t u = (k & 0x80000000u) ? (k & 0x7FFFFFFFu) : ~k;
    return __uint_as_float(u);
}
__device__ __forceinline__ float max4(float4 x) {
    return fmaxf(fmaxf(x.x, x.y), fmaxf(x.z, x.w));
}
__device__ __forceinline__ void pushg(float v, int idx, int row) {
    int p = atomicAdd(&gCnt[row], 1);
    if (p < CAP)
        gCand[row * CAP + p] =
            ((unsigned long long)f2key(v) << 32) | (uint32_t)(~(uint32_t)idx);
}
__device__ __forceinline__ void collect4g(float4 x, int base, float T, int row) {
    if (max4(x) >= T) {   // rarely taken
        if (x.x >= T) pushg(x.x, base + 0, row);
        if (x.y >= T) pushg(x.y, base + 1, row);
        if (x.z >= T) pushg(x.z, base + 2, row);
        if (x.w >= T) pushg(x.w, base + 3, row);
    }
}

// ============ Kernel 1: streaming pass (512 CTAs, one wave) — measured 13.6us
__global__ __launch_bounds__(T1THREADS, 6)
void pass_kernel(const float* __restrict__ logits, int V)
{
    __shared__ float sWs[T1THREADS / 32];

    const int tid   = threadIdx.x;
    const int lane  = tid & 31;
    const int wid   = tid >> 5;
    const int row   = blockIdx.x / SPLITS;
    const int split = blockIdx.x % SPLITS;

    const float* rowp = logits + (long long)row * V;

    int chunk = (((V + SPLITS - 1) / SPLITS) + 3) & ~3;   // multiple of 4
    int start = split * chunk;
    int end   = start + chunk; if (end > V) end = V;
    if (start >= end) { if (tid == 0) gPart[row * SPLITS + split] = 0.f; return; }

    const float4* r4 = reinterpret_cast<const float4*>(rowp);
    const int s4 = start >> 2;
    const int e4 = end   >> 2;

    float a0 = 0.f, a1 = 0.f, a2 = 0.f, a3 = 0.f;
    int vi = s4 + tid;
    for (; vi + 3 * T1THREADS < e4; vi += 4 * T1THREADS) {
        float4 x0 = r4[vi];
        float4 x1 = r4[vi +     T1THREADS];
        float4 x2 = r4[vi + 2 * T1THREADS];
        float4 x3 = r4[vi + 3 * T1THREADS];

        a0 += __expf(x0.x); a1 += __expf(x0.y); a2 += __expf(x0.z); a3 += __expf(x0.w);
        a0 += __expf(x1.x); a1 += __expf(x1.y); a2 += __expf(x1.z); a3 += __expf(x1.w);
        a0 += __expf(x2.x); a1 += __expf(x2.y); a2 += __expf(x2.z); a3 += __expf(x2.w);
        a0 += __expf(x3.x); a1 += __expf(x3.y); a2 += __expf(x3.z); a3 += __expf(x3.w);

        collect4g(x0,  vi                  << 2, T_INIT, row);
        collect4g(x1, (vi +     T1THREADS) << 2, T_INIT, row);
        collect4g(x2, (vi + 2 * T1THREADS) << 2, T_INIT, row);
        collect4g(x3, (vi + 3 * T1THREADS) << 2, T_INIT, row);
    }
    for (; vi < e4; vi += T1THREADS) {
        float4 x0 = r4[vi];
        a0 += __expf(x0.x); a1 += __expf(x0.y); a2 += __expf(x0.z); a3 += __expf(x0.w);
        collect4g(x0, vi << 2, T_INIT, row);
    }
    for (int i = (e4 << 2) + tid; i < end; i += T1THREADS) {
        float x = rowp[i];
        a0 += __expf(x);
        if (x >= T_INIT) pushg(x, i, row);
    }

    float s = (a0 + a1) + (a2 + a3);
    #pragma unroll
    for (int off = 16; off; off >>= 1)
        s += __shfl_xor_sync(0xffffffffu, s, off);
    if (lane == 0) sWs[wid] = s;
    __syncthreads();
    if (tid == 0) {
        float S = 0.f;
        #pragma unroll
        for (int w = 0; w < T1THREADS / 32; w++) S += sWs[w];
        gPart[row * SPLITS + split] = S;
    }
}

// ============ Kernel 2: PDL finish — prologue overlaps the pass ==============
__global__ __launch_bounds__(T2THREADS, 4)
void finish_kernel(const float* __restrict__ logits,
                   const int*   __restrict__ top_ks,
                   const float* __restrict__ top_ps,
                   const float* __restrict__ min_ps,
                   const float* __restrict__ uvec,
                   float* __restrict__ out,
                   int B, int V, int K)
{
    __shared__ unsigned long long sCand[CAP];
    __shared__ uint32_t sKey[TOPN];
    __shared__ int      sIdx[TOPN];
    __shared__ float    sP[TOPN];
    __shared__ float    sS;
    __shared__ int      sNsh;
    __shared__ int   sTopk;
    __shared__ float sTp, sMp, sU;

    const int tid = threadIdx.x;
    const int row = blockIdx.x;
    const float* rowp = logits + (long long)row * V;

    // -------- PROLOGUE (runs concurrently with pass_kernel under PDL) --------
    if (tid == 0)  sTopk = top_ks[row];
    if (tid == 32) sTp   = top_ps[row];
    if (tid == 64) sMp   = min_ps[row];
    if (tid == 96) sU    = uvec[row];
    if (tid < TOPN) { sKey[tid] = 0u; sIdx[tid] = 0; }
    __syncthreads();

    // -------- wait for the pass grid (implicit trigger at its completion) ----
    asm volatile("griddepcontrol.wait;" ::: "memory");

    if (tid == 0) sNsh = gCnt[row];
    if (tid == 32) {
        float S = 0.f;
        #pragma unroll
        for (int p = 0; p < SPLITS; p++) S += gPart[row * SPLITS + p];
        sS = S;
    }
    __syncthreads();
    int n = sNsh;

    // ---- deterministic fallback rescan (never taken for this data) ----
    float T = T_INIT;
    for (int att = 0; att < 8 && (n < TOPN || n > CAP); att++) {
        T = (n < TOPN) ? (T - 1.5f) : (T + 1.25f);
        __syncthreads();
        if (tid == 0) gCnt[row] = 0;
        __syncthreads();
        const float4* r4 = reinterpret_cast<const float4*>(rowp);
        const int nvec = V >> 2;
        for (int vi = tid; vi < nvec; vi += T2THREADS)
            collect4g(r4[vi], vi << 2, T, row);
        for (int i = (nvec << 2) + tid; i < V; i += T2THREADS) {
            float x = rowp[i];
            if (x >= T) pushg(x, i, row);
        }
        __syncthreads();
        if (tid == 0) sNsh = gCnt[row];
        __syncthreads();
        n = sNsh;
    }
    if (n > CAP) n = CAP;

    // ---- stage candidates to shared ----
    for (int i = tid; i < n; i += T2THREADS)
        sCand[i] = gCand[row * CAP + i];
    __syncthreads();

    // ---- exact rank (value desc, index asc via ~idx in low bits) ----
    for (int i = tid; i < n; i += T2THREADS) {
        unsigned long long mine = sCand[i];
        int rnk = 0;
        for (int j = 0; j < n; j++) rnk += (sCand[j] > mine) ? 1 : 0;
        if (rnk < TOPN) {
            sKey[rnk] = (uint32_t)(mine >> 32);
            sIdx[rnk] = (int)(~(uint32_t)mine);
        }
    }
    __syncthreads();

    // ---- parallel prob precompute + top-K outputs ----
    const float S = sS;
    if (tid < TOPN)
        sP[tid] = __expf(key2f(sKey[tid])) / S;
    if (tid < K) {
        float logZ = logf(S);
        out[B + (long long)row * K + tid] = key2f(sKey[tid]) - logZ;
        out[B + (long long)B * K + (long long)row * K + tid] = (float)sIdx[tid];
    }
    __syncthreads();

    // ---- serial-ORDER epilogue, fully unrolled (LDS batched, FADD order kept)
    if (tid == 0) {
        int   topk = sTopk;
        float tp = sTp;
        float mp = sMp;
        float uu = sU;

        // loop 1: min-p threshold + masked total (exclusive-cumsum keep rule)
        float cum = 0.f, total = 0.f, thresh = 0.f;
        #pragma unroll
        for (int j = 0; j < TOPN; j++) {
            float p = sP[j];
            bool keep = (j < topk) && (cum <= tp);
            cum += p;
            if (j == 0) thresh = p * mp;
            float mj = keep ? p : 0.f;
            if (mj < thresh) mj = 0.f;
            total += mj;
        }
        // loop 2: recompute identical masked values; count cdf < target
        float target = uu * total;
        float cdf = 0.f;
        int pos = 0;
        cum = 0.f;
        #pragma unroll
        for (int j = 0; j < TOPN; j++) {
            float p = sP[j];
            bool keep = (j < topk) && (cum <= tp);
            cum += p;
            float mj = keep ? p : 0.f;
            if (mj < thresh) mj = 0.f;
            cdf += mj;
            pos += (cdf < target) ? 1 : 0;
        }
        if (pos > TOPN - 1) pos = TOPN - 1;
        out[row] = (float)sIdx[pos];

        gCnt[row] = 0;   // restore invariant for next (graph-replayed) launch
    }
}

extern "C" void kernel_launch(void* const* d_in, const int* in_sizes, int n_in,
                              void* d_out, int out_size) {
    const float* logits = (const float*)d_in[0];
    const int*   top_ks = (const int*)d_in[1];
    const float* top_ps = (const float*)d_in[2];
    const float* min_ps = (const float*)d_in[3];
    const float* u      = (const float*)d_in[4];

    int B = in_sizes[1];
    int V = in_sizes[0] / B;
    int K = (out_size - B) / (2 * B);

    pass_kernel<<<B * SPLITS, T1THREADS>>>(logits, V);

    // finish launched with PDL: its prologue overlaps the pass
    cudaLaunchConfig_t cfg = {};
    cfg.gridDim  = dim3(B);
    cfg.blockDim = dim3(T2THREADS);
    cfg.dynamicSmemBytes = 0;
    cfg.stream = 0;
    cudaLaunchAttribute attrs[1];
    attrs[0].id = cudaLaunchAttributeProgrammaticStreamSerialization;
    attrs[0].val.programmaticStreamSerializationAllowed = 1;
    cfg.attrs = attrs;
    cfg.numAttrs = 1;
    cudaLaunchKernelEx(&cfg, finish_kernel, logits, top_ks, top_ps, min_ps, u,
                       (float*)d_out, B, V, K);
}

// round 17
// speedup vs baseline: 1.2166x; 1.2166x over previous
#include <cuda_runtime.h>
#include <cooperative_groups.h>
#include <cstdint>

namespace cg = cooperative_groups;

#define CLUSTER  2
#define THREADS  512
#define NWARPS   (THREADS / 32)
#define TOPN     64
#define CAP      1024
#define T_INIT   6.0f

__device__ __forceinline__ uint32_t f2key(float x) {
    uint32_t u = __float_as_uint(x);
    return (u & 0x80000000u) ? ~u : (u | 0x80000000u);
}
__device__ __forceinline__ float key2f(uint32_t k) {
    uint32_t u = (k & 0x80000000u) ? (k & 0x7FFFFFFFu) : ~k;
    return __uint_as_float(u);
}
__device__ __forceinline__ float max4(float4 x) {
    return fmaxf(fmaxf(x.x, x.y), fmaxf(x.z, x.w));
}

__global__ __launch_bounds__(THREADS, 2) __cluster_dims__(CLUSTER, 1, 1)
void sampler_kernel(const float* __restrict__ logits,
                    const int*   __restrict__ top_ks,
                    const float* __restrict__ top_ps,
                    const float* __restrict__ min_ps,
                    const float* __restrict__ uvec,
                    float* __restrict__ out,
                    int B, int V, int K)
{
    __shared__ unsigned long long sCand[CAP];
    __shared__ int      sN;
    __shared__ float    sPart[CLUSTER];
    __shared__ float    sWs[NWARPS];
    __shared__ uint32_t sKey[TOPN];
    __shared__ int      sIdx[TOPN];
    __shared__ float    sP[TOPN];

    cg::cluster_group cluster = cg::this_cluster();
    const unsigned rank = cluster.block_rank();
    const int tid  = threadIdx.x;
    const int lane = tid & 31;
    const int wid  = tid >> 5;
    const int row  = blockIdx.x / CLUSTER;

    if (tid == 0) sN = 0;
    if (tid < TOPN) { sKey[tid] = 0u; sIdx[tid] = 0; }
    cluster.sync();   // rank0's sN initialized before any remote pushes

    // DSMEM pointers into rank 0's shared memory
    int* rN = cluster.map_shared_rank(&sN, 0);
    unsigned long long* rCand = cluster.map_shared_rank(sCand, 0);
    float* rPart = cluster.map_shared_rank(sPart, 0);

    const float*  rowp = logits + (long long)row * V;
    const float4* r4   = reinterpret_cast<const float4*>(rowp);
    const int nvec = V >> 2;

    // ---------------- streaming pass over this CTA's half-row ---------------
    const int chunk4 = (nvec + CLUSTER - 1) / CLUSTER;
    const int s4 = (int)rank * chunk4;
    const int e4 = min(s4 + chunk4, nvec);

    float a0 = 0.f, a1 = 0.f, a2 = 0.f, a3 = 0.f;
    int vi = s4 + tid;
    for (; vi + 3 * THREADS < e4; vi += 4 * THREADS) {
        float4 x0 = r4[vi];
        float4 x1 = r4[vi +     THREADS];
        float4 x2 = r4[vi + 2 * THREADS];
        float4 x3 = r4[vi + 3 * THREADS];

        a0 += __expf(x0.x); a1 += __expf(x0.y); a2 += __expf(x0.z); a3 += __expf(x0.w);
        a0 += __expf(x1.x); a1 += __expf(x1.y); a2 += __expf(x1.z); a3 += __expf(x1.w);
        a0 += __expf(x2.x); a1 += __expf(x2.y); a2 += __expf(x2.z); a3 += __expf(x2.w);
        a0 += __expf(x3.x); a1 += __expf(x3.y); a2 += __expf(x3.z); a3 += __expf(x3.w);

        float mx = fmaxf(fmaxf(max4(x0), max4(x1)), fmaxf(max4(x2), max4(x3)));
        if (mx >= T_INIT) {   // rarely taken
            #pragma unroll
            for (int b = 0; b < 4; b++) {
                float4 x = (b == 0) ? x0 : (b == 1) ? x1 : (b == 2) ? x2 : x3;
                int base = (vi + b * THREADS) << 2;
                if (x.x >= T_INIT) { int p = atomicAdd(rN, 1); if (p < CAP) rCand[p] = ((unsigned long long)f2key(x.x) << 32) | (uint32_t)(~(uint32_t)(base + 0)); }
                if (x.y >= T_INIT) { int p = atomicAdd(rN, 1); if (p < CAP) rCand[p] = ((unsigned long long)f2key(x.y) << 32) | (uint32_t)(~(uint32_t)(base + 1)); }
                if (x.z >= T_INIT) { int p = atomicAdd(rN, 1); if (p < CAP) rCand[p] = ((unsigned long long)f2key(x.z) << 32) | (uint32_t)(~(uint32_t)(base + 2)); }
                if (x.w >= T_INIT) { int p = atomicAdd(rN, 1); if (p < CAP) rCand[p] = ((unsigned long long)f2key(x.w) << 32) | (uint32_t)(~(uint32_t)(base + 3)); }
            }
        }
    }
    for (; vi < e4; vi += THREADS) {
        float4 x = r4[vi];
        a0 += __expf(x.x); a1 += __expf(x.y); a2 += __expf(x.z); a3 += __expf(x.w);
        if (max4(x) >= T_INIT) {
            int base = vi << 2;
            if (x.x >= T_INIT) { int p = atomicAdd(rN, 1); if (p < CAP) rCand[p] = ((unsigned long long)f2key(x.x) << 32) | (uint32_t)(~(uint32_t)(base + 0)); }
            if (x.y >= T_INIT) { int p = atomicAdd(rN, 1); if (p < CAP) rCand[p] = ((unsigned long long)f2key(x.y) << 32) | (uint32_t)(~(uint32_t)(base + 1)); }
            if (x.z >= T_INIT) { int p = atomicAdd(rN, 1); if (p < CAP) rCand[p] = ((unsigned long long)f2key(x.z) << 32) | (uint32_t)(~(uint32_t)(base + 2)); }
            if (x.w >= T_INIT) { int p = atomicAdd(rN, 1); if (p < CAP) rCand[p] = ((unsigned long long)f2key(x.w) << 32) | (uint32_t)(~(uint32_t)(base + 3)); }
        }
    }
    // scalar tail (V % 4) handled by rank 0
    if (rank == 0) {
        for (int i = (nvec << 2) + tid; i < V; i += THREADS) {
            float x = rowp[i];
            a0 += __expf(x);
            if (x >= T_INIT) { int p = atomicAdd(rN, 1); if (p < CAP) rCand[p] = ((unsigned long long)f2key(x) << 32) | (uint32_t)(~(uint32_t)i); }
        }
    }

    // ---- CTA reduce of sum(exp), publish to rank0 DSMEM slot ----
    float s = (a0 + a1) + (a2 + a3);
    #pragma unroll
    for (int off = 16; off; off >>= 1)
        s += __shfl_xor_sync(0xffffffffu, s, off);
    if (lane == 0) sWs[wid] = s;
    __syncthreads();
    if (tid == 0) {
        float S = 0.f;
        #pragma unroll
        for (int w = 0; w < NWARPS; w++) S += sWs[w];
        rPart[rank] = S;   // fixed slot -> deterministic combine order
    }
    cluster.sync();        // all pushes + partials visible to rank 0
    if (rank != 0) return;

    // =================== FINISH (rank 0, all data in own shared) ============
    float S = 0.f;
    #pragma unroll
    for (int p = 0; p < CLUSTER; p++) S += sPart[p];
    int n = sN;

    // ---- deterministic fallback rescan over the full row (never taken) ----
    float T = T_INIT;
    for (int att = 0; att < 8 && (n < TOPN || n > CAP); att++) {
        T = (n < TOPN) ? (T - 1.5f) : (T + 1.25f);
        __syncthreads();
        if (tid == 0) sN = 0;
        __syncthreads();
        for (int v2 = tid; v2 < nvec; v2 += THREADS) {
            float4 x = r4[v2];
            if (max4(x) >= T) {
                int base = v2 << 2;
                if (x.x >= T) { int p = atomicAdd(&sN, 1); if (p < CAP) sCand[p] = ((unsigned long long)f2key(x.x) << 32) | (uint32_t)(~(uint32_t)(base + 0)); }
                if (x.y >= T) { int p = atomicAdd(&sN, 1); if (p < CAP) sCand[p] = ((unsigned long long)f2key(x.y) << 32) | (uint32_t)(~(uint32_t)(base + 1)); }
                if (x.z >= T) { int p = atomicAdd(&sN, 1); if (p < CAP) sCand[p] = ((unsigned long long)f2key(x.z) << 32) | (uint32_t)(~(uint32_t)(base + 2)); }
                if (x.w >= T) { int p = atomicAdd(&sN, 1); if (p < CAP) sCand[p] = ((unsigned long long)f2key(x.w) << 32) | (uint32_t)(~(uint32_t)(base + 3)); }
            }
        }
        for (int i = (nvec << 2) + tid; i < V; i += THREADS) {
            float x = rowp[i];
            if (x >= T) { int p = atomicAdd(&sN, 1); if (p < CAP) sCand[p] = ((unsigned long long)f2key(x) << 32) | (uint32_t)(~(uint32_t)i); }
        }
        __syncthreads();
        n = sN;
    }
    if (n > CAP) n = CAP;
    __syncthreads();

    // ---- exact rank among candidates (value desc, index asc on ties) ----
    for (int i = tid; i < n; i += THREADS) {
        unsigned long long mine = sCand[i];
        int rnk = 0;
        for (int j = 0; j < n; j++) rnk += (sCand[j] > mine) ? 1 : 0;
        if (rnk < TOPN) {
            sKey[rnk] = (uint32_t)(mine >> 32);
            sIdx[rnk] = (int)(~(uint32_t)mine);
        }
    }
    __syncthreads();

    // ---- parallel prob precompute + top-K outputs ----
    if (tid < TOPN)
        sP[tid] = __expf(key2f(sKey[tid])) / S;
    if (tid < K) {
        float logZ = logf(S);
        out[B + (long long)row * K + tid] = key2f(sKey[tid]) - logZ;
        out[B + (long long)B * K + (long long)row * K + tid] = (float)sIdx[tid];
    }
    __syncthreads();

    // ---- serial-ORDER epilogue, fully unrolled (validated fp order) ----
    if (tid == 0) {
        int   topk = top_ks[row];
        float tp = top_ps[row];
        float mp = min_ps[row];
        float uu = uvec[row];

        // loop 1: min-p threshold + masked total (exclusive-cumsum keep rule)
        float cum = 0.f, total = 0.f, thresh = 0.f;
        #pragma unroll
        for (int j = 0; j < TOPN; j++) {
            float p = sP[j];
            bool keep = (j < topk) && (cum <= tp);
            cum += p;
            if (j == 0) thresh = p * mp;
            float mj = keep ? p : 0.f;
            if (mj < thresh) mj = 0.f;
            total += mj;
        }
        // loop 2: recompute identical masked values; count cdf < target
        float target = uu * total;
        float cdf = 0.f;
        int pos = 0;
        cum = 0.f;
        #pragma unroll
        for (int j = 0; j < TOPN; j++) {
            float p = sP[j];
            bool keep = (j < topk) && (cum <= tp);
            cum += p;
            float mj = keep ? p : 0.f;
            if (mj < thresh) mj = 0.f;
            cdf += mj;
            pos += (cdf < target) ? 1 : 0;
        }
        if (pos > TOPN - 1) pos = TOPN - 1;
        out[row] = (float)sIdx[pos];
    }
}

extern "C" void kernel_launch(void* const* d_in, const int* in_sizes, int n_in,
                              void* d_out, int out_size) {
    const float* logits = (const float*)d_in[0];
    const int*   top_ks = (const int*)d_in[1];
    const float* top_ps = (const float*)d_in[2];
    const float* min_ps = (const float*)d_in[3];
    const float* u      = (const float*)d_in[4];

    int B = in_sizes[1];
    int V = in_sizes[0] / B;
    int K = (out_size - B) / (2 * B);

    sampler_kernel<<<B * CLUSTER, THREADS>>>(logits, top_ks, top_ps, min_ps, u,
                                             (float*)d_out, B, V, K);
}